// round 9
// baseline (speedup 1.0000x reference)
#include <cuda_runtime.h>
#include <cstdint>
#include <cstddef>

#define NCAP 50048
#define ECAP 800256

static __device__ float g_Y1   [(size_t)ECAP*4];
static __device__ float g_wattn[(size_t)ECAP*320];
static __device__ float g_Hsum [(size_t)NCAP*64];
static __device__ float g_G    [(size_t)NCAP*192];
static __device__ float g_Ysum [(size_t)NCAP*3];
static __device__ float g_deg  [NCAP];
static __device__ float g_f0a  [(size_t)NCAP*64];
static __device__ float g_f1a  [(size_t)NCAP*192];
static __device__ float g_z    [NCAP*8];
static __device__ float g_agg0 [(size_t)NCAP*64];
static __device__ float g_agg1 [(size_t)NCAP*192];
static __device__ float g_M0[4096], g_M1[4096], g_bv0[64], g_bv1[64];

#define RBF_START 0.006737946999085467f
#define RBF_STEP  ((1.0f - RBF_START) / 49.0f)
#define RBF_BETA  (1.0f/((0.04f*(1.0f-RBF_START))*(0.04f*(1.0f-RBF_START))))
#define INV_DEG   0.25f
#define INV_SQRT3 0.5773502691896258f
#define INV_SQRT2 0.7071067811865476f
#define PI_OVER_CUT 0.6283185307179586f

__device__ __forceinline__ float siluf(float x){ return x/(1.f+__expf(-x)); }
__device__ __forceinline__ float sigmf(float x){ return 1.f/(1.f+__expf(-x)); }
__device__ __forceinline__ void red4(float* p, float4 v){
    asm volatile("red.global.add.v4.f32 [%0], {%1,%2,%3,%4};"
                 ::"l"(p),"f"(v.x),"f"(v.y),"f"(v.z),"f"(v.w):"memory");
}
__device__ __forceinline__ void tf32split(float v, float& hi, float& lo){
    unsigned h; asm("cvt.rna.tf32.f32 %0,%1;":"=r"(h):"f"(v));
    hi=__uint_as_float(h);
    unsigned l; asm("cvt.rna.tf32.f32 %0,%1;":"=r"(l):"f"(v-hi));
    lo=__uint_as_float(l);
}
#define MMA_T(d,a0,a1,a2,a3,b0,b1) \
    asm volatile("mma.sync.aligned.m16n8k8.row.col.f32.tf32.tf32.f32 " \
        "{%0,%1,%2,%3},{%4,%5,%6,%7},{%8,%9},{%0,%1,%2,%3};" \
        :"+f"(d[0]),"+f"(d[1]),"+f"(d[2]),"+f"(d[3]) \
        :"r"(a0),"r"(a1),"r"(a2),"r"(a3),"r"(b0),"r"(b1))

// 3xTF32 GEMM: warp computes 16x32 tile. A: [row][k] stride 68. W: [k][n] stride 72.
// Fragments (m16n8k8): a0(g,tg) a1(g+8,tg) a2(g,tg+4) a3(g+8,tg+4);
// b0(k=tg,n=g) b1(k=tg+4,n=g); d0(g,2tg) d1(g,2tg+1) d2(g+8,2tg) d3(g+8,2tg+1).
__device__ __forceinline__ void mma_gemm(
    const float* __restrict__ AH, const float* __restrict__ AL,
    const float* __restrict__ WH, const float* __restrict__ WL,
    int ksteps, int rb, int ch, int g, int tg, float acc[4][4]){
    for(int ks=0; ks<ksteps; ks++){
        int k0=ks*8;
        int r0=(rb*16+g)*68+k0+tg, r1=r0+8*68;
        unsigned ah0=__float_as_uint(AH[r0]),   ah1=__float_as_uint(AH[r1]);
        unsigned ah2=__float_as_uint(AH[r0+4]), ah3=__float_as_uint(AH[r1+4]);
        unsigned al0=__float_as_uint(AL[r0]),   al1=__float_as_uint(AL[r1]);
        unsigned al2=__float_as_uint(AL[r0+4]), al3=__float_as_uint(AL[r1+4]);
#pragma unroll
        for(int tt=0;tt<4;tt++){
            int b0i=(k0+tg)*72+ch*32+tt*8+g, b1i=b0i+4*72;
            unsigned bh0=__float_as_uint(WH[b0i]), bh1=__float_as_uint(WH[b1i]);
            unsigned bl0=__float_as_uint(WL[b0i]), bl1=__float_as_uint(WL[b1i]);
            MMA_T(acc[tt],ah0,ah1,ah2,ah3,bh0,bh1);
            MMA_T(acc[tt],ah0,ah1,ah2,ah3,bl0,bl1);
            MMA_T(acc[tt],al0,al1,al2,al3,bh0,bh1);
        }
    }
}
#define ACC_ZEROF(acc) {_Pragma("unroll") for(int j=0;j<4;j++){_Pragma("unroll") for(int c=0;c<4;c++) acc[j][c]=0.f;}}

__global__ void k_zero(int N){
    size_t i=(size_t)blockIdx.x*blockDim.x+threadIdx.x, st=(size_t)gridDim.x*blockDim.x;
    for(size_t j=i;j<(size_t)N*64;j+=st){ g_Hsum[j]=0.f; g_agg0[j]=0.f; }
    for(size_t j=i;j<(size_t)N*192;j+=st){ g_G[j]=0.f; g_agg1[j]=0.f; }
    for(size_t j=i;j<(size_t)N*8;j+=st) g_z[j]=0.f;
    for(size_t j=i;j<(size_t)N*3;j+=st) g_Ysum[j]=0.f;
    for(size_t j=i;j<(size_t)N;j+=st) g_deg[j]=0.f;
}

__global__ void k_prep(const float* __restrict__ Wdeg, const float* __restrict__ bdeg,
                       const float* __restrict__ ew,
                       const float* __restrict__ P0, const float* __restrict__ P1){
    for(int idx=blockIdx.x*256+threadIdx.x; idx<8320; idx+=8*256){
        if(idx<4096){ int h=idx>>6,d=idx&63; float s=0.f;
            for(int c=0;c<64;c++) s+=Wdeg[h*128+c]*ew[c]*P0[c*64+d];
            g_M0[idx]=s;
        }else if(idx<8192){ int i2=idx-4096,h=i2>>6,d=i2&63; float s=0.f;
            for(int c=0;c<64;c++) s+=Wdeg[h*128+64+c]*ew[c]*P1[c*64+d];
            g_M1[i2]=s;
        }else if(idx<8256){ int d=idx-8192; float s=0.f;
            for(int c=0;c<64;c++) s+=bdeg[c]*ew[c]*P0[c*64+d];
            g_bv0[d]=s;
        }else{ int d=idx-8256; float s=0.f;
            for(int c=0;c<64;c++) s+=bdeg[64+c]*ew[c]*P1[c*64+d];
            g_bv1[d]=s;
        }
    }
}

// K1: 64 edges/block, tensor-core GEMMs (3xTF32).
// dyn smem floats: PH 0, PL 4352, QH 8704, QL 13056, WH 17408(64x72), WL 22016; total 26624 fl = 106496 B
__global__ __launch_bounds__(256) void k_edge(
    const float* __restrict__ pos, const int* __restrict__ esrc, const int* __restrict__ edst,
    const float* __restrict__ W1, const float* __restrict__ b1,
    const float* __restrict__ W2, const float* __restrict__ b2,
    const float* __restrict__ Wattn, const float* __restrict__ battn, int E){
    extern __shared__ float dyn[];
    float* PH=dyn;        float* PL=dyn+4352;
    float* QH=dyn+8704;   float* QL=dyn+13056;
    float* WH=dyn+17408;  float* WL=dyn+22016;
    __shared__ int sDst[64];
    __shared__ float sY1[64][4], sCut[64], sExp[64];
    const int t=threadIdx.x, eBase=blockIdx.x*64;
    const int lane=t&31, wid=t>>5, g=lane>>2, tg=lane&3;
    const int rb=wid&3, ch=wid>>2;

    if(t<64){
        int ge=eBase+t;
        if(ge<E){
            int s=esrc[ge], d=edst[ge];
            float vx=pos[d*3+0]-pos[s*3+0], vy=pos[d*3+1]-pos[s*3+1], vz=pos[d*3+2]-pos[s*3+2];
            float d2=vx*vx+vy*vy+vz*vz+1e-9f;
            float id=rsqrtf(d2), dist=d2*id;
            float yx=vx*id, yy=vy*id, yz=vz*id;
            float cut=(dist<5.0f)?0.5f*(__cosf(dist*PI_OVER_CUT)+1.0f):0.0f;
            sDst[t]=d; sY1[t][0]=yx; sY1[t][1]=yy; sY1[t][2]=yz; sY1[t][3]=0.f;
            sCut[t]=cut; sExp[t]=__expf(-dist);
            *(float4*)&g_Y1[(size_t)ge*4]=make_float4(yx,yy,yz,dist);
        }else{
            sDst[t]=0; sY1[t][0]=sY1[t][1]=sY1[t][2]=sY1[t][3]=0.f; sCut[t]=0.f; sExp[t]=0.f;
        }
    }
    __syncthreads();
    // stage rbf (64x56, zeros k>=50) into PH/PL and W1 (56x64, zero rows>=50) into WH/WL
    for(int idx=t; idx<64*56; idx+=256){
        int e=idx/56, k=idx-e*56; float v=0.f;
        if(k<50){ float tt2=sExp[e]-(RBF_START+(float)k*RBF_STEP); v=sCut[e]*__expf(-RBF_BETA*tt2*tt2); }
        float hi,lo; tf32split(v,hi,lo);
        PH[e*68+k]=hi; PL[e*68+k]=lo;
    }
    for(int idx=t; idx<56*64; idx+=256){
        int r=idx>>6, c=idx&63;
        float v=(r<50)?W1[r*64+c]:0.f;
        float hi,lo; tf32split(v,hi,lo);
        WH[r*72+c]=hi; WL[r*72+c]=lo;
    }
    __syncthreads();
    { // GEMM1: h1 = silu(rbf@W1+b1) -> Q
        float acc[4][4]; ACC_ZEROF(acc);
        mma_gemm(PH,PL,WH,WL,7,rb,ch,g,tg,acc);
#pragma unroll
        for(int tt=0;tt<4;tt++){
            int row0=rb*16+g, row1=row0+8, col=ch*32+tt*8+2*tg;
            float2 bb=*(const float2*)&b1[col];
            float v00=siluf(acc[tt][0]+bb.x), v01=siluf(acc[tt][1]+bb.y);
            float v10=siluf(acc[tt][2]+bb.x), v11=siluf(acc[tt][3]+bb.y);
            float hi,lo;
            tf32split(v00,hi,lo); QH[row0*68+col]=hi;   QL[row0*68+col]=lo;
            tf32split(v01,hi,lo); QH[row0*68+col+1]=hi; QL[row0*68+col+1]=lo;
            tf32split(v10,hi,lo); QH[row1*68+col]=hi;   QL[row1*68+col]=lo;
            tf32split(v11,hi,lo); QH[row1*68+col+1]=hi; QL[row1*68+col+1]=lo;
        }
    }
    __syncthreads();
    for(int idx=t; idx<4096; idx+=256){
        int r=idx>>6, c=idx&63;
        float hi,lo; tf32split(W2[idx],hi,lo);
        WH[r*72+c]=hi; WL[r*72+c]=lo;
    }
    __syncthreads();
    { // GEMM2: hmid = silu(h1@W2+b2) -> P
        float acc[4][4]; ACC_ZEROF(acc);
        mma_gemm(QH,QL,WH,WL,8,rb,ch,g,tg,acc);
#pragma unroll
        for(int tt=0;tt<4;tt++){
            int row0=rb*16+g, row1=row0+8, col=ch*32+tt*8+2*tg;
            float2 bb=*(const float2*)&b2[col];
            float v00=siluf(acc[tt][0]+bb.x), v01=siluf(acc[tt][1]+bb.y);
            float v10=siluf(acc[tt][2]+bb.x), v11=siluf(acc[tt][3]+bb.y);
            float hi,lo;
            tf32split(v00,hi,lo); PH[row0*68+col]=hi;   PL[row0*68+col]=lo;
            tf32split(v01,hi,lo); PH[row0*68+col+1]=hi; PL[row0*68+col+1]=lo;
            tf32split(v10,hi,lo); PH[row1*68+col]=hi;   PL[row1*68+col]=lo;
            tf32split(v11,hi,lo); PH[row1*68+col+1]=hi; PL[row1*68+col+1]=lo;
        }
    }
    __syncthreads();
    { // degree scatter: hmid = PH+PL
        int e=t>>2, q=t&3;
        if(eBase+e<E){
            int d=sDst[e];
            float yx=sY1[e][0], yy=sY1[e][1], yz=sY1[e][2];
#pragma unroll
            for(int m=0;m<4;m++){
                int c=q*16+m*4;
                float4 h4=*(const float4*)(PH+(size_t)e*68+c);
                float4 l4=*(const float4*)(PL+(size_t)e*68+c);
                h4.x+=l4.x; h4.y+=l4.y; h4.z+=l4.z; h4.w+=l4.w;
                red4(&g_Hsum[(size_t)d*64+c], h4);
                red4(&g_G[(size_t)d*192+c],     make_float4(h4.x*yx,h4.y*yx,h4.z*yx,h4.w*yx));
                red4(&g_G[(size_t)d*192+64+c],  make_float4(h4.x*yy,h4.y*yy,h4.z*yy,h4.w*yy));
                red4(&g_G[(size_t)d*192+128+c], make_float4(h4.x*yz,h4.y*yz,h4.z*yz,h4.w*yz));
            }
        }
        if(t<64 && eBase+t<E){
            int d=sDst[t];
            atomicAdd(&g_deg[d],1.0f);
            atomicAdd(&g_Ysum[(size_t)d*3+0],sY1[t][0]);
            atomicAdd(&g_Ysum[(size_t)d*3+1],sY1[t][1]);
            atomicAdd(&g_Ysum[(size_t)d*3+2],sY1[t][2]);
        }
    }
    for(int p=0;p<5;p++){ // Wattn passes -> g_wattn
        __syncthreads();
        for(int idx=t; idx<4096; idx+=256){
            int r=idx>>6, c=idx&63;
            float hi,lo; tf32split(Wattn[(size_t)r*320+p*64+c],hi,lo);
            WH[r*72+c]=hi; WL[r*72+c]=lo;
        }
        __syncthreads();
        float acc[4][4]; ACC_ZEROF(acc);
        mma_gemm(PH,PL,WH,WL,8,rb,ch,g,tg,acc);
#pragma unroll
        for(int tt=0;tt<4;tt++){
            int row0=rb*16+g, row1=row0+8, col=ch*32+tt*8+2*tg;
            float2 bb=*(const float2*)&battn[p*64+col];
            int ge0=eBase+row0, ge1=eBase+row1;
            if(ge0<E) *(float2*)&g_wattn[(size_t)ge0*320+p*64+col]=
                make_float2(acc[tt][0]+bb.x,acc[tt][1]+bb.y);
            if(ge1<E) *(float2*)&g_wattn[(size_t)ge1*320+p*64+col]=
                make_float2(acc[tt][2]+bb.x,acc[tt][3]+bb.y);
        }
    }
}

// K2: batched 64 nodes/block (SIMT 4x4 tiles). dyn smem: A(4352)+M0(4096)+M1(4096)=50176B
__device__ __forceinline__ void tile_gemm(const float* __restrict__ As,
                                          const float* __restrict__ Ws,
                                          int KK, int eg, int cg, float acc[4][4]){
    for(int k=0;k<KK;k+=4){
        float4 av[4];
#pragma unroll
        for(int j=0;j<4;j++) av[j]=*(const float4*)(As+(size_t)(eg*4+j)*68+k);
        float4 wv[4];
#pragma unroll
        for(int kk=0;kk<4;kk++) wv[kk]=*(const float4*)(Ws+(size_t)(k+kk)*64+cg*4);
#pragma unroll
        for(int j=0;j<4;j++){
            acc[j][0]+=av[j].x*wv[0].x+av[j].y*wv[1].x+av[j].z*wv[2].x+av[j].w*wv[3].x;
            acc[j][1]+=av[j].x*wv[0].y+av[j].y*wv[1].y+av[j].z*wv[2].y+av[j].w*wv[3].y;
            acc[j][2]+=av[j].x*wv[0].z+av[j].y*wv[1].z+av[j].z*wv[2].z+av[j].w*wv[3].z;
            acc[j][3]+=av[j].x*wv[0].w+av[j].y*wv[1].w+av[j].z*wv[2].w+av[j].w*wv[3].w;
        }
    }
}

__global__ __launch_bounds__(256) void k_node_deg(
    const float* __restrict__ embW, const int* __restrict__ atom, int N){
    extern __shared__ float dyn[];
    float* A=dyn; float* M0s=dyn+4352; float* M1s=dyn+8448;
    __shared__ float sbv0[64], sbv1[64], sDeg[64], sYs[3][64];
    __shared__ int sAtom[64];
    const int t=threadIdx.x, nb=blockIdx.x*64, cg=t&15, eg=t>>4;
    for(int idx=t; idx<4096; idx+=256){ M0s[idx]=g_M0[idx]; M1s[idx]=g_M1[idx]; }
    if(t<64){
        sbv0[t]=g_bv0[t]; sbv1[t]=g_bv1[t];
        int n=nb+t; bool v=n<N;
        sDeg[t]=v?g_deg[n]:0.f;
        sYs[0][t]=v?g_Ysum[(size_t)n*3+0]:0.f;
        sYs[1][t]=v?g_Ysum[(size_t)n*3+1]:0.f;
        sYs[2][t]=v?g_Ysum[(size_t)n*3+2]:0.f;
        sAtom[t]=v?atom[n]:0;
    }
    for(int idx=t; idx<4096; idx+=256){
        int n=idx>>6, k=idx&63;
        A[n*68+k]=(nb+n<N)?g_Hsum[(size_t)(nb+n)*64+k]:0.f;
    }
    __syncthreads();
    {
        float acc[4][4]; ACC_ZEROF(acc);
        tile_gemm(A,M0s,64,eg,cg,acc);
#pragma unroll
        for(int j=0;j<4;j++){
            int ln=eg*4+j, n=nb+ln;
            if(n<N){
                float dg=sDeg[ln];
                float4 ev=*(const float4*)(embW+(size_t)sAtom[ln]*64+cg*4);
                float4 o;
                o.x=ev.x+INV_DEG*(acc[j][0]+dg*sbv0[cg*4+0]);
                o.y=ev.y+INV_DEG*(acc[j][1]+dg*sbv0[cg*4+1]);
                o.z=ev.z+INV_DEG*(acc[j][2]+dg*sbv0[cg*4+2]);
                o.w=ev.w+INV_DEG*(acc[j][3]+dg*sbv0[cg*4+3]);
                *(float4*)&g_f0a[(size_t)n*64+cg*4]=o;
            }
        }
    }
    for(int i=0;i<3;i++){
        __syncthreads();
        for(int idx=t; idx<4096; idx+=256){
            int n=idx>>6, k=idx&63;
            A[n*68+k]=(nb+n<N)?g_G[(size_t)(nb+n)*192+i*64+k]:0.f;
        }
        __syncthreads();
        float acc[4][4]; ACC_ZEROF(acc);
        tile_gemm(A,M1s,64,eg,cg,acc);
#pragma unroll
        for(int j=0;j<4;j++){
            int ln=eg*4+j, n=nb+ln;
            if(n<N){
                float ys=sYs[i][ln];
                float4 o;
                o.x=INV_DEG*(acc[j][0]+ys*sbv1[cg*4+0]);
                o.y=INV_DEG*(acc[j][1]+ys*sbv1[cg*4+1]);
                o.z=INV_DEG*(acc[j][2]+ys*sbv1[cg*4+2]);
                o.w=INV_DEG*(acc[j][3]+ys*sbv1[cg*4+3]);
                *(float4*)&g_f1a[(size_t)n*192+i*64+cg*4]=o;
            }
        }
    }
}

// K3: warp-per-edge messages + exp + direct weighted scatter
__global__ __launch_bounds__(256) void k_msg(
    const int* __restrict__ esrc, const int* __restrict__ edst,
    const float* __restrict__ ad, int E){
    __shared__ float sMsg[8][256];
    const int w=threadIdx.x>>5, lane=threadIdx.x&31;
    const int e=blockIdx.x*8+w;
    if(e>=E) return;
    const int src=esrc[e], dst=edst[e];
    float4 y4=*(const float4*)&g_Y1[(size_t)e*4];
    const float yx=y4.x, yy=y4.y, yz=y4.z;
    const int c0=lane, c1=lane+32;
    float s0a=g_f0a[(size_t)src*64+c0], s0b=g_f0a[(size_t)src*64+c1];
    float s1a0=g_f1a[(size_t)src*192+c0],     s1b0=g_f1a[(size_t)src*192+c1];
    float s1a1=g_f1a[(size_t)src*192+64+c0],  s1b1=g_f1a[(size_t)src*192+64+c1];
    float s1a2=g_f1a[(size_t)src*192+128+c0], s1b2=g_f1a[(size_t)src*192+128+c1];
    const float* wp=g_wattn+(size_t)e*320;
    float w0a=wp[c0],w0b=wp[c1],w1a=wp[64+c0],w1b=wp[64+c1];
    float w2a=wp[128+c0],w2b=wp[128+c1],w3a=wp[192+c0],w3b=wp[192+c1];
    float w4a=wp[256+c0],w4b=wp[256+c1];
    float d1a=s1a0*yx+s1a1*yy+s1a2*yz;
    float d1b=s1b0*yx+s1b1*yy+s1b2*yz;
    float m0a=w0a*s0a+w3a*d1a*INV_SQRT3;
    float m0b=w0b*s0b+w3b*d1b*INV_SQRT3;
    float cxa=s1a1*yz-s1a2*yy, cya=s1a2*yx-s1a0*yz, cza=s1a0*yy-s1a1*yx;
    float cxb=s1b1*yz-s1b2*yy, cyb=s1b2*yx-s1b0*yz, czb=s1b0*yy-s1b1*yx;
    float m1a0=w1a*s0a*yx+w2a*s1a0+w4a*cxa*INV_SQRT2;
    float m1a1=w1a*s0a*yy+w2a*s1a1+w4a*cya*INV_SQRT2;
    float m1a2=w1a*s0a*yz+w2a*s1a2+w4a*cza*INV_SQRT2;
    float m1b0=w1b*s0b*yx+w2b*s1b0+w4b*cxb*INV_SQRT2;
    float m1b1=w1b*s0b*yy+w2b*s1b1+w4b*cyb*INV_SQRT2;
    float m1b2=w1b*s0b*yz+w2b*s1b2+w4b*czb*INV_SQRT2;
    float slra=0.2f*m0a+0.8f*m0a*sigmf(m0a);
    float slrb=0.2f*m0b+0.8f*m0b*sigmf(m0b);
    float p0=slra*__ldg(&ad[c0]);
    float p1=slrb*__ldg(&ad[c1]);
#pragma unroll
    for(int off=1;off<8;off<<=1){
        p0+=__shfl_xor_sync(0xffffffffu,p0,off);
        p1+=__shfl_xor_sync(0xffffffffu,p1,off);
    }
    float ea0=__expf(p0), ea1=__expf(p1);
    if((lane&7)==0){
        atomicAdd(&g_z[dst*8+(lane>>3)],  ea0);
        atomicAdd(&g_z[dst*8+4+(lane>>3)],ea1);
    }
    float* myMsg=sMsg[w];
    myMsg[lane]     =ea0*m0a;  myMsg[lane+32]    =ea1*m0b;
    myMsg[64+lane]  =ea0*m1a0; myMsg[64+lane+32] =ea1*m1b0;
    myMsg[128+lane] =ea0*m1a1; myMsg[128+lane+32]=ea1*m1b1;
    myMsg[192+lane] =ea0*m1a2; myMsg[192+lane+32]=ea1*m1b2;
    __syncwarp();
#pragma unroll
    for(int rq=0;rq<2;rq++){
        int q=lane+rq*32;
        float* dp;
        if(q<16) dp=g_agg0+(size_t)dst*64+q*4;
        else{ int rr=q-16, i=rr>>4, cq=rr&15; dp=g_agg1+(size_t)dst*192+i*64+cq*4; }
        red4(dp, *(const float4*)(myMsg+q*4));
    }
}

// K6: node output. dyn smem floats: 28864 (=115456B)
__global__ __launch_bounds__(256) void k_out(
    const float* __restrict__ P0o, const float* __restrict__ P1o,
    const float* __restrict__ W1s, const float* __restrict__ b1s,
    const float* __restrict__ W1v, const float* __restrict__ W2s,
    const float* __restrict__ b2s, const float* __restrict__ W2v,
    float* __restrict__ out, int N){
    extern __shared__ float dyn[];
    float* sP0=dyn; float* sP1=dyn+4096; float* sW1s=dyn+8192; float* sW1v=dyn+16384;
    float* sW2s=dyn+20480; float* sW2v=dyn+24576; float* sb1=dyn+28672; float* sb2=dyn+28800;
    __shared__ float sA[8][64], sB[8][192], sF0[8][64], sF1[8][192], sT0[8][64];
    const int t=threadIdx.x;
    for(int idx=t; idx<4096; idx+=256){
        sP0[idx]=P0o[idx]; sP1[idx]=P1o[idx];
        sW1v[idx]=W1v[idx]; sW2s[idx]=W2s[idx]; sW2v[idx]=W2v[idx];
    }
    for(int idx=t; idx<8192; idx+=256) sW1s[idx]=W1s[idx];
    if(t<128) sb1[t]=b1s[t];
    if(t<64)  sb2[t]=b2s[t];
    __syncthreads();
    const int w=t>>5, lane=t&31, n=blockIdx.x*8+w;
    if(n>=N) return;
    float* A_=sA[w]; float* B_=sB[w]; float* F0=sF0[w]; float* F1=sF1[w]; float* T0_=sT0[w];
    {
        float z0=g_z[n*8+(lane>>3)], z1=g_z[n*8+4+(lane>>3)];
        float iz0=(z0>0.f)?1.f/z0:0.f, iz1=(z1>0.f)?1.f/z1:0.f;
        A_[lane]   =g_agg0[(size_t)n*64+lane]*iz0;
        A_[lane+32]=g_agg0[(size_t)n*64+lane+32]*iz1;
#pragma unroll
        for(int m=0;m<6;m++){
            int j=m*32+lane, cc=j&63;
            float zz=g_z[n*8+(cc>>3)];
            B_[j]=g_agg1[(size_t)n*192+j]*((zz>0.f)?1.f/zz:0.f);
        }
    }
    __syncwarp();
    {
        float a0=g_f0a[(size_t)n*64+lane], a1=g_f0a[(size_t)n*64+lane+32];
#pragma unroll 8
        for(int h=0;h<64;h++){ float av=A_[h]; a0+=av*sP0[h*64+lane]; a1+=av*sP0[h*64+lane+32]; }
        F0[lane]=a0; F0[lane+32]=a1;
    }
#pragma unroll
    for(int i=0;i<3;i++){
        float a0=g_f1a[(size_t)n*192+i*64+lane], a1=g_f1a[(size_t)n*192+i*64+lane+32];
#pragma unroll 8
        for(int c=0;c<64;c++){ float bv=B_[i*64+c]; a0+=bv*sP1[c*64+lane]; a1+=bv*sP1[c*64+lane+32]; }
        F1[i*64+lane]=a0; F1[i*64+lane+32]=a1;
    }
    __syncwarp();
    {
        float hsa=sb1[lane], hga=sb1[64+lane], hsb=sb1[lane+32], hgb=sb1[96+lane];
#pragma unroll 8
        for(int c=0;c<64;c++){
            float f=F0[c];
            hsa+=f*sW1s[c*128+lane];    hga+=f*sW1s[c*128+64+lane];
            hsb+=f*sW1s[c*128+lane+32]; hgb+=f*sW1s[c*128+96+lane];
        }
        T0_[lane]=siluf(hsa); T0_[lane+32]=siluf(hsb);
        A_[lane]=sigmf(hga);  A_[lane+32]=sigmf(hgb);
    }
    __syncwarp();
#pragma unroll
    for(int i=0;i<3;i++){
        float m0=0.f, m1=0.f;
#pragma unroll 8
        for(int c=0;c<64;c++){ float f=F1[i*64+c]; m0+=f*sW1v[c*64+lane]; m1+=f*sW1v[c*64+lane+32]; }
        B_[i*64+lane]=m0*A_[lane]; B_[i*64+lane+32]=m1*A_[lane+32];
    }
    __syncwarp();
    {
        float o0=F0[lane]+sb2[lane], o1=F0[lane+32]+sb2[lane+32];
#pragma unroll 8
        for(int c=0;c<64;c++){ float m=T0_[c]; o0+=m*sW2s[c*64+lane]; o1+=m*sW2s[c*64+lane+32]; }
        out[(size_t)n*256+lane]=o0; out[(size_t)n*256+lane+32]=o1;
    }
#pragma unroll
    for(int i=0;i<3;i++){
        float o0=F1[i*64+lane], o1=F1[i*64+lane+32];
#pragma unroll 8
        for(int c=0;c<64;c++){ float m=B_[i*64+c]; o0+=m*sW2v[c*64+lane]; o1+=m*sW2v[c*64+lane+32]; }
        out[(size_t)n*256+64+lane*3+i]=o0;
        out[(size_t)n*256+64+(lane+32)*3+i]=o1;
    }
}

extern "C" void kernel_launch(void* const* d_in, const int* in_sizes, int n_in,
                              void* d_out, int out_size){
    const float* pos   =(const float*)d_in[0];
    const float* embW  =(const float*)d_in[1];
    const float* expw  =(const float*)d_in[2];
    const float* W1    =(const float*)d_in[3];
    const float* b1    =(const float*)d_in[4];
    const float* W2    =(const float*)d_in[5];
    const float* b2    =(const float*)d_in[6];
    const float* Wdeg  =(const float*)d_in[7];
    const float* bdeg  =(const float*)d_in[8];
    const float* Wattn =(const float*)d_in[9];
    const float* battn =(const float*)d_in[10];
    const float* P0    =(const float*)d_in[11];
    const float* P1    =(const float*)d_in[12];
    const float* ad    =(const float*)d_in[13];
    const float* P0o   =(const float*)d_in[14];
    const float* P1o   =(const float*)d_in[15];
    const float* W1s   =(const float*)d_in[16];
    const float* b1s   =(const float*)d_in[17];
    const float* W1v   =(const float*)d_in[18];
    const float* W2s   =(const float*)d_in[19];
    const float* b2s   =(const float*)d_in[20];
    const float* W2v   =(const float*)d_in[21];
    const int*   atom  =(const int*)d_in[22];
    const int*   esrc  =(const int*)d_in[23];
    const int*   edst  =(const int*)d_in[24];
    float* out=(float*)d_out;
    const int N=in_sizes[0]/3;
    const int E=in_sizes[23];

    static int attr_done=0;
    if(!attr_done){
        cudaFuncSetAttribute(k_edge,     cudaFuncAttributeMaxDynamicSharedMemorySize, 106496);
        cudaFuncSetAttribute(k_node_deg, cudaFuncAttributeMaxDynamicSharedMemorySize, 50176);
        cudaFuncSetAttribute(k_out,      cudaFuncAttributeMaxDynamicSharedMemorySize, 115456);
        attr_done=1;
    }

    k_zero<<<512,256>>>(N);
    k_prep<<<8,256>>>(Wdeg,bdeg,expw,P0,P1);
    k_edge<<<(E+63)/64,256,106496>>>(pos,esrc,edst,W1,b1,W2,b2,Wattn,battn,E);
    k_node_deg<<<(N+63)/64,256,50176>>>(embW,atom,N);
    k_msg<<<(E+7)/8,256>>>(esrc,edst,ad,E);
    k_out<<<(N+7)/8,256,115456>>>(P0o,P1o,W1s,b1s,W1v,W2s,b2s,W2v,out,N);
}

// round 12
// speedup vs baseline: 1.2679x; 1.2679x over previous
#include <cuda_runtime.h>
#include <cstdint>
#include <cstddef>

#define NCAP 50048
#define ECAP 800256

static __device__ float g_Y1   [(size_t)ECAP*4];
static __device__ float g_wattn[(size_t)ECAP*320];
static __device__ float g_Hsum [(size_t)NCAP*64];
static __device__ float g_G    [(size_t)NCAP*192];
static __device__ float g_Ysum [(size_t)NCAP*3];
static __device__ float g_deg  [NCAP];
static __device__ float g_f0a  [(size_t)NCAP*64];
static __device__ float g_f1a  [(size_t)NCAP*192];
static __device__ float g_z    [NCAP*8];
static __device__ float g_agg0 [(size_t)NCAP*64];
static __device__ float g_agg1 [(size_t)NCAP*192];
static __device__ float g_M0[4096], g_M1[4096], g_bv0[64], g_bv1[64];

#define RBF_START 0.006737946999085467f
#define RBF_STEP  ((1.0f - RBF_START) / 49.0f)
#define RBF_BETA  (1.0f/((0.04f*(1.0f-RBF_START))*(0.04f*(1.0f-RBF_START))))
#define INV_DEG   0.25f
#define INV_SQRT3 0.5773502691896258f
#define INV_SQRT2 0.7071067811865476f
#define PI_OVER_CUT 0.6283185307179586f

__device__ __forceinline__ float siluf(float x){ return x/(1.f+__expf(-x)); }
__device__ __forceinline__ float sigmf(float x){ return 1.f/(1.f+__expf(-x)); }
__device__ __forceinline__ void red4(float* p, float4 v){
    asm volatile("red.global.add.v4.f32 [%0], {%1,%2,%3,%4};"
                 ::"l"(p),"f"(v.x),"f"(v.y),"f"(v.z),"f"(v.w):"memory");
}

// scalar 4x4 tile GEMM: A rows stride 68, Ws row-major [k][64] (2B/FMA, crossbar-balanced)
__device__ __forceinline__ void tile_gemm(const float* __restrict__ As,
                                          const float* __restrict__ Ws,
                                          int KK, int eg, int cg, float acc[4][4]){
    for(int k=0;k<KK;k+=4){
        float4 av[4];
#pragma unroll
        for(int j=0;j<4;j++) av[j]=*(const float4*)(As+(size_t)(eg*4+j)*68+k);
        float4 wv[4];
#pragma unroll
        for(int kk=0;kk<4;kk++) wv[kk]=*(const float4*)(Ws+(size_t)(k+kk)*64+cg*4);
#pragma unroll
        for(int j=0;j<4;j++){
            acc[j][0]+=av[j].x*wv[0].x+av[j].y*wv[1].x+av[j].z*wv[2].x+av[j].w*wv[3].x;
            acc[j][1]+=av[j].x*wv[0].y+av[j].y*wv[1].y+av[j].z*wv[2].y+av[j].w*wv[3].y;
            acc[j][2]+=av[j].x*wv[0].z+av[j].y*wv[1].z+av[j].z*wv[2].z+av[j].w*wv[3].z;
            acc[j][3]+=av[j].x*wv[0].w+av[j].y*wv[1].w+av[j].z*wv[2].w+av[j].w*wv[3].w;
        }
    }
}
#define ACC_ZEROF(acc) {_Pragma("unroll") for(int j=0;j<4;j++){_Pragma("unroll") for(int c=0;c<4;c++) acc[j][c]=0.f;}}

__global__ void k_zero(int N){
    size_t i=(size_t)blockIdx.x*blockDim.x+threadIdx.x, st=(size_t)gridDim.x*blockDim.x;
    for(size_t j=i;j<(size_t)N*64;j+=st){ g_Hsum[j]=0.f; g_agg0[j]=0.f; }
    for(size_t j=i;j<(size_t)N*192;j+=st){ g_G[j]=0.f; g_agg1[j]=0.f; }
    for(size_t j=i;j<(size_t)N*8;j+=st) g_z[j]=0.f;
    for(size_t j=i;j<(size_t)N*3;j+=st) g_Ysum[j]=0.f;
    for(size_t j=i;j<(size_t)N;j+=st) g_deg[j]=0.f;
}

__global__ void k_prep(const float* __restrict__ Wdeg, const float* __restrict__ bdeg,
                       const float* __restrict__ ew,
                       const float* __restrict__ P0, const float* __restrict__ P1){
    for(int idx=blockIdx.x*256+threadIdx.x; idx<8320; idx+=8*256){
        if(idx<4096){ int h=idx>>6,d=idx&63; float s=0.f;
            for(int c=0;c<64;c++) s+=Wdeg[h*128+c]*ew[c]*P0[c*64+d];
            g_M0[idx]=s;
        }else if(idx<8192){ int i2=idx-4096,h=i2>>6,d=i2&63; float s=0.f;
            for(int c=0;c<64;c++) s+=Wdeg[h*128+64+c]*ew[c]*P1[c*64+d];
            g_M1[i2]=s;
        }else if(idx<8256){ int d=idx-8192; float s=0.f;
            for(int c=0;c<64;c++) s+=bdeg[c]*ew[c]*P0[c*64+d];
            g_bv0[d]=s;
        }else{ int d=idx-8256; float s=0.f;
            for(int c=0;c<64;c++) s+=bdeg[64+c]*ew[c]*P1[c*64+d];
            g_bv1[d]=s;
        }
    }
}

// K1: 64 edges/block. dyn smem: A(64*68)+B(64*68)+Ws(4096) = 51200 B
__global__ __launch_bounds__(256) void k_edge(
    const float* __restrict__ pos, const int* __restrict__ esrc, const int* __restrict__ edst,
    const float* __restrict__ W1, const float* __restrict__ b1,
    const float* __restrict__ W2, const float* __restrict__ b2,
    const float* __restrict__ Wattn, const float* __restrict__ battn, int E){
    extern __shared__ float dyn[];
    float* A=dyn; float* B=dyn+64*68; float* Ws=dyn+2*64*68;
    __shared__ int sDst[64];
    __shared__ float sY1[64][4], sCut[64], sExp[64];
    const int t=threadIdx.x, eBase=blockIdx.x*64, cg=t&15, eg=t>>4;

    if(t<64){
        int ge=eBase+t;
        if(ge<E){
            int s=esrc[ge], d=edst[ge];
            float vx=pos[d*3+0]-pos[s*3+0], vy=pos[d*3+1]-pos[s*3+1], vz=pos[d*3+2]-pos[s*3+2];
            float d2=vx*vx+vy*vy+vz*vz+1e-9f;
            float id=rsqrtf(d2), dist=d2*id;
            float yx=vx*id, yy=vy*id, yz=vz*id;
            float cut=(dist<5.0f)?0.5f*(__cosf(dist*PI_OVER_CUT)+1.0f):0.0f;
            sDst[t]=d; sY1[t][0]=yx; sY1[t][1]=yy; sY1[t][2]=yz; sY1[t][3]=0.f;
            sCut[t]=cut; sExp[t]=__expf(-dist);
            *(float4*)&g_Y1[(size_t)ge*4]=make_float4(yx,yy,yz,dist);
        }else{
            sDst[t]=0; sY1[t][0]=sY1[t][1]=sY1[t][2]=sY1[t][3]=0.f; sCut[t]=0.f; sExp[t]=0.f;
        }
    }
    __syncthreads();
    for(int idx=t; idx<64*52; idx+=256){
        int e=idx/52, k=idx-e*52; float v=0.f;
        if(k<50){ float tt=sExp[e]-(RBF_START+(float)k*RBF_STEP); v=sCut[e]*__expf(-RBF_BETA*tt*tt); }
        A[e*68+k]=v;
    }
    for(int idx=t; idx<52*64; idx+=256){ int r=idx>>6; Ws[idx]=(r<50)?W1[idx]:0.f; }
    __syncthreads();
    { // GEMM1 -> B
        float acc[4][4]; ACC_ZEROF(acc);
        tile_gemm(A,Ws,52,eg,cg,acc);
        float4 bb=*(const float4*)(b1+cg*4);
#pragma unroll
        for(int j=0;j<4;j++){
            float* r=B+(size_t)(eg*4+j)*68+cg*4;
            r[0]=siluf(acc[j][0]+bb.x); r[1]=siluf(acc[j][1]+bb.y);
            r[2]=siluf(acc[j][2]+bb.z); r[3]=siluf(acc[j][3]+bb.w);
        }
    }
    __syncthreads();
    for(int idx=t; idx<4096; idx+=256) Ws[idx]=W2[idx];
    __syncthreads();
    { // GEMM2 -> A (hmid)
        float acc[4][4]; ACC_ZEROF(acc);
        tile_gemm(B,Ws,64,eg,cg,acc);
        float4 bb=*(const float4*)(b2+cg*4);
#pragma unroll
        for(int j=0;j<4;j++){
            float* r=A+(size_t)(eg*4+j)*68+cg*4;
            r[0]=siluf(acc[j][0]+bb.x); r[1]=siluf(acc[j][1]+bb.y);
            r[2]=siluf(acc[j][2]+bb.z); r[3]=siluf(acc[j][3]+bb.w);
        }
    }
    __syncthreads();
    { // degree scatter
        int e=t>>2, q=t&3;
        if(eBase+e<E){
            int d=sDst[e];
            float yx=sY1[e][0], yy=sY1[e][1], yz=sY1[e][2];
#pragma unroll
            for(int m=0;m<4;m++){
                int c=q*16+m*4;
                float4 h4=*(const float4*)(A+(size_t)e*68+c);
                red4(&g_Hsum[(size_t)d*64+c], h4);
                red4(&g_G[(size_t)d*192+c],     make_float4(h4.x*yx,h4.y*yx,h4.z*yx,h4.w*yx));
                red4(&g_G[(size_t)d*192+64+c],  make_float4(h4.x*yy,h4.y*yy,h4.z*yy,h4.w*yy));
                red4(&g_G[(size_t)d*192+128+c], make_float4(h4.x*yz,h4.y*yz,h4.z*yz,h4.w*yz));
            }
        }
        if(t<64 && eBase+t<E){
            int d=sDst[t];
            atomicAdd(&g_deg[d],1.0f);
            atomicAdd(&g_Ysum[(size_t)d*3+0],sY1[t][0]);
            atomicAdd(&g_Ysum[(size_t)d*3+1],sY1[t][1]);
            atomicAdd(&g_Ysum[(size_t)d*3+2],sY1[t][2]);
        }
    }
    for(int p=0;p<5;p++){ // Wattn passes
        __syncthreads();
        for(int idx=t; idx<4096; idx+=256){
            int r=idx>>6, c=idx&63;
            Ws[idx]=Wattn[(size_t)r*320+p*64+c];
        }
        __syncthreads();
        float acc[4][4]; ACC_ZEROF(acc);
        tile_gemm(A,Ws,64,eg,cg,acc);
        float4 bb=*(const float4*)(battn+p*64+cg*4);
#pragma unroll
        for(int j=0;j<4;j++){
            int ge=eBase+eg*4+j;
            if(ge<E)
                *(float4*)&g_wattn[(size_t)ge*320+p*64+cg*4]=
                    make_float4(acc[j][0]+bb.x,acc[j][1]+bb.y,acc[j][2]+bb.z,acc[j][3]+bb.w);
        }
    }
}

// K2: batched 64 nodes/block. dyn smem: A(4352)+M0(4096)+M1(4096)=50176B
__global__ __launch_bounds__(256) void k_node_deg(
    const float* __restrict__ embW, const int* __restrict__ atom, int N){
    extern __shared__ float dyn[];
    float* A=dyn; float* M0s=dyn+4352; float* M1s=dyn+8448;
    __shared__ float sbv0[64], sbv1[64], sDeg[64], sYs[3][64];
    __shared__ int sAtom[64];
    const int t=threadIdx.x, nb=blockIdx.x*64, cg=t&15, eg=t>>4;
    for(int idx=t; idx<4096; idx+=256){ M0s[idx]=g_M0[idx]; M1s[idx]=g_M1[idx]; }
    if(t<64){
        sbv0[t]=g_bv0[t]; sbv1[t]=g_bv1[t];
        int n=nb+t; bool v=n<N;
        sDeg[t]=v?g_deg[n]:0.f;
        sYs[0][t]=v?g_Ysum[(size_t)n*3+0]:0.f;
        sYs[1][t]=v?g_Ysum[(size_t)n*3+1]:0.f;
        sYs[2][t]=v?g_Ysum[(size_t)n*3+2]:0.f;
        sAtom[t]=v?atom[n]:0;
    }
    for(int idx=t; idx<4096; idx+=256){
        int n=idx>>6, k=idx&63;
        A[n*68+k]=(nb+n<N)?g_Hsum[(size_t)(nb+n)*64+k]:0.f;
    }
    __syncthreads();
    {
        float acc[4][4]; ACC_ZEROF(acc);
        tile_gemm(A,M0s,64,eg,cg,acc);
#pragma unroll
        for(int j=0;j<4;j++){
            int ln=eg*4+j, n=nb+ln;
            if(n<N){
                float dg=sDeg[ln];
                float4 ev=*(const float4*)(embW+(size_t)sAtom[ln]*64+cg*4);
                float4 o;
                o.x=ev.x+INV_DEG*(acc[j][0]+dg*sbv0[cg*4+0]);
                o.y=ev.y+INV_DEG*(acc[j][1]+dg*sbv0[cg*4+1]);
                o.z=ev.z+INV_DEG*(acc[j][2]+dg*sbv0[cg*4+2]);
                o.w=ev.w+INV_DEG*(acc[j][3]+dg*sbv0[cg*4+3]);
                *(float4*)&g_f0a[(size_t)n*64+cg*4]=o;
            }
        }
    }
    for(int i=0;i<3;i++){
        __syncthreads();
        for(int idx=t; idx<4096; idx+=256){
            int n=idx>>6, k=idx&63;
            A[n*68+k]=(nb+n<N)?g_G[(size_t)(nb+n)*192+i*64+k]:0.f;
        }
        __syncthreads();
        float acc[4][4]; ACC_ZEROF(acc);
        tile_gemm(A,M1s,64,eg,cg,acc);
#pragma unroll
        for(int j=0;j<4;j++){
            int ln=eg*4+j, n=nb+ln;
            if(n<N){
                float ys=sYs[i][ln];
                float4 o;
                o.x=INV_DEG*(acc[j][0]+ys*sbv1[cg*4+0]);
                o.y=INV_DEG*(acc[j][1]+ys*sbv1[cg*4+1]);
                o.z=INV_DEG*(acc[j][2]+ys*sbv1[cg*4+2]);
                o.w=INV_DEG*(acc[j][3]+ys*sbv1[cg*4+3]);
                *(float4*)&g_f1a[(size_t)n*192+i*64+cg*4]=o;
            }
        }
    }
}

// K3: warp-per-edge messages + exp + direct weighted scatter
__global__ __launch_bounds__(256) void k_msg(
    const int* __restrict__ esrc, const int* __restrict__ edst,
    const float* __restrict__ ad, int E){
    __shared__ float sMsg[8][256];
    const int w=threadIdx.x>>5, lane=threadIdx.x&31;
    const int e=blockIdx.x*8+w;
    if(e>=E) return;
    const int src=esrc[e], dst=edst[e];
    float4 y4=*(const float4*)&g_Y1[(size_t)e*4];
    const float yx=y4.x, yy=y4.y, yz=y4.z;
    const int c0=lane, c1=lane+32;
    float s0a=g_f0a[(size_t)src*64+c0], s0b=g_f0a[(size_t)src*64+c1];
    float s1a0=g_f1a[(size_t)src*192+c0],     s1b0=g_f1a[(size_t)src*192+c1];
    float s1a1=g_f1a[(size_t)src*192+64+c0],  s1b1=g_f1a[(size_t)src*192+64+c1];
    float s1a2=g_f1a[(size_t)src*192+128+c0], s1b2=g_f1a[(size_t)src*192+128+c1];
    const float* wp=g_wattn+(size_t)e*320;
    float w0a=wp[c0],w0b=wp[c1],w1a=wp[64+c0],w1b=wp[64+c1];
    float w2a=wp[128+c0],w2b=wp[128+c1],w3a=wp[192+c0],w3b=wp[192+c1];
    float w4a=wp[256+c0],w4b=wp[256+c1];
    float d1a=s1a0*yx+s1a1*yy+s1a2*yz;
    float d1b=s1b0*yx+s1b1*yy+s1b2*yz;
    float m0a=w0a*s0a+w3a*d1a*INV_SQRT3;
    float m0b=w0b*s0b+w3b*d1b*INV_SQRT3;
    float cxa=s1a1*yz-s1a2*yy, cya=s1a2*yx-s1a0*yz, cza=s1a0*yy-s1a1*yx;
    float cxb=s1b1*yz-s1b2*yy, cyb=s1b2*yx-s1b0*yz, czb=s1b0*yy-s1b1*yx;
    float m1a0=w1a*s0a*yx+w2a*s1a0+w4a*cxa*INV_SQRT2;
    float m1a1=w1a*s0a*yy+w2a*s1a1+w4a*cya*INV_SQRT2;
    float m1a2=w1a*s0a*yz+w2a*s1a2+w4a*cza*INV_SQRT2;
    float m1b0=w1b*s0b*yx+w2b*s1b0+w4b*cxb*INV_SQRT2;
    float m1b1=w1b*s0b*yy+w2b*s1b1+w4b*cyb*INV_SQRT2;
    float m1b2=w1b*s0b*yz+w2b*s1b2+w4b*czb*INV_SQRT2;
    float slra=0.2f*m0a+0.8f*m0a*sigmf(m0a);
    float slrb=0.2f*m0b+0.8f*m0b*sigmf(m0b);
    float p0=slra*__ldg(&ad[c0]);
    float p1=slrb*__ldg(&ad[c1]);
#pragma unroll
    for(int off=1;off<8;off<<=1){
        p0+=__shfl_xor_sync(0xffffffffu,p0,off);
        p1+=__shfl_xor_sync(0xffffffffu,p1,off);
    }
    float ea0=__expf(p0), ea1=__expf(p1);
    if((lane&7)==0){
        atomicAdd(&g_z[dst*8+(lane>>3)],  ea0);
        atomicAdd(&g_z[dst*8+4+(lane>>3)],ea1);
    }
    float* myMsg=sMsg[w];
    myMsg[lane]     =ea0*m0a;  myMsg[lane+32]    =ea1*m0b;
    myMsg[64+lane]  =ea0*m1a0; myMsg[64+lane+32] =ea1*m1b0;
    myMsg[128+lane] =ea0*m1a1; myMsg[128+lane+32]=ea1*m1b1;
    myMsg[192+lane] =ea0*m1a2; myMsg[192+lane+32]=ea1*m1b2;
    __syncwarp();
#pragma unroll
    for(int rq=0;rq<2;rq++){
        int q=lane+rq*32;
        float* dp;
        if(q<16) dp=g_agg0+(size_t)dst*64+q*4;
        else{ int rr=q-16, i=rr>>4, cq=rr&15; dp=g_agg1+(size_t)dst*192+i*64+cq*4; }
        red4(dp, *(const float4*)(myMsg+q*4));
    }
}

// K6: batched 64 nodes/block, tile GEMMs.
// dyn smem floats: A 0, F0 4352, T 8704, G 13056, Ws 17408, IZ 21504; total 22016 fl = 88064 B
__global__ __launch_bounds__(256) void k_out(
    const float* __restrict__ P0o, const float* __restrict__ P1o,
    const float* __restrict__ W1s, const float* __restrict__ b1s,
    const float* __restrict__ W1v, const float* __restrict__ W2s,
    const float* __restrict__ b2s, const float* __restrict__ W2v,
    float* __restrict__ out, int N){
    extern __shared__ float dyn[];
    float* A=dyn; float* F0=dyn+4352; float* T=dyn+8704; float* G=dyn+13056;
    float* Ws=dyn+17408; float* IZ=dyn+21504;
    const int t=threadIdx.x, nb=blockIdx.x*64, cg=t&15, eg=t>>4;

    // inverse z per (node, head) — strided loop covers all 512 entries
    for(int idx=t; idx<512; idx+=256){
        int n=idx>>3, h=idx&7;
        float z=(nb+n<N)?g_z[(nb+n)*8+h]:0.f;
        IZ[idx]=(z>0.f)?1.f/z:0.f;
    }
    for(int idx=t; idx<4096; idx+=256) Ws[idx]=P0o[idx];
    __syncthreads();
    for(int idx=t; idx<4096; idx+=256){
        int n=idx>>6, c=idx&63;
        A[n*68+c]=(nb+n<N)?g_agg0[(size_t)(nb+n)*64+c]*IZ[n*8+(c>>3)]:0.f;
    }
    __syncthreads();
    { // F0 = f0a + agg0n @ P0o
        float acc[4][4]; ACC_ZEROF(acc);
        tile_gemm(A,Ws,64,eg,cg,acc);
#pragma unroll
        for(int j=0;j<4;j++){
            int ln=eg*4+j, n=nb+ln;
            float4 f=(n<N)?*(const float4*)&g_f0a[(size_t)n*64+cg*4]:make_float4(0,0,0,0);
            float* r=F0+(size_t)ln*68+cg*4;
            r[0]=f.x+acc[j][0]; r[1]=f.y+acc[j][1]; r[2]=f.z+acc[j][2]; r[3]=f.w+acc[j][3];
        }
    }
    // mid_s = silu(F0@W1s[:, :64] + b1s[:64]) -> T
    __syncthreads();
    for(int idx=t; idx<4096; idx+=256) Ws[idx]=W1s[(size_t)(idx>>6)*128+(idx&63)];
    __syncthreads();
    {
        float acc[4][4]; ACC_ZEROF(acc);
        tile_gemm(F0,Ws,64,eg,cg,acc);
        float4 bb=*(const float4*)&b1s[cg*4];
#pragma unroll
        for(int j=0;j<4;j++){
            float* r=T+(size_t)(eg*4+j)*68+cg*4;
            r[0]=siluf(acc[j][0]+bb.x); r[1]=siluf(acc[j][1]+bb.y);
            r[2]=siluf(acc[j][2]+bb.z); r[3]=siluf(acc[j][3]+bb.w);
        }
    }
    // gate = sigmoid(F0@W1s[:, 64:] + b1s[64:]) -> G
    __syncthreads();
    for(int idx=t; idx<4096; idx+=256) Ws[idx]=W1s[(size_t)(idx>>6)*128+64+(idx&63)];
    __syncthreads();
    {
        float acc[4][4]; ACC_ZEROF(acc);
        tile_gemm(F0,Ws,64,eg,cg,acc);
        float4 bb=*(const float4*)&b1s[64+cg*4];
#pragma unroll
        for(int j=0;j<4;j++){
            float* r=G+(size_t)(eg*4+j)*68+cg*4;
            r[0]=sigmf(acc[j][0]+bb.x); r[1]=sigmf(acc[j][1]+bb.y);
            r[2]=sigmf(acc[j][2]+bb.z); r[3]=sigmf(acc[j][3]+bb.w);
        }
    }
    // out0 = F0 + mid_s@W2s + b2s
    __syncthreads();
    for(int idx=t; idx<4096; idx+=256) Ws[idx]=W2s[idx];
    __syncthreads();
    {
        float acc[4][4]; ACC_ZEROF(acc);
        tile_gemm(T,Ws,64,eg,cg,acc);
        float4 bb=*(const float4*)&b2s[cg*4];
#pragma unroll
        for(int j=0;j<4;j++){
            int ln=eg*4+j, n=nb+ln;
            if(n<N){
                const float* f=F0+(size_t)ln*68+cg*4;
                *(float4*)&out[(size_t)n*256+cg*4]=make_float4(
                    f[0]+acc[j][0]+bb.x, f[1]+acc[j][1]+bb.y,
                    f[2]+acc[j][2]+bb.z, f[3]+acc[j][3]+bb.w);
            }
        }
    }
    // vector path per i: F1i (F0 slot), MV (T slot)
    for(int i=0;i<3;i++){
        __syncthreads();
        for(int idx=t; idx<4096; idx+=256) Ws[idx]=P1o[idx];
        for(int idx=t; idx<4096; idx+=256){
            int n=idx>>6, c=idx&63;
            A[n*68+c]=(nb+n<N)?g_agg1[(size_t)(nb+n)*192+i*64+c]*IZ[n*8+(c>>3)]:0.f;
        }
        __syncthreads();
        { // F1i = f1a_i + agg1n_i @ P1o -> F0 slot
            float acc[4][4]; ACC_ZEROF(acc);
            tile_gemm(A,Ws,64,eg,cg,acc);
#pragma unroll
            for(int j=0;j<4;j++){
                int ln=eg*4+j, n=nb+ln;
                float4 f=(n<N)?*(const float4*)&g_f1a[(size_t)n*192+i*64+cg*4]:make_float4(0,0,0,0);
                float* r=F0+(size_t)ln*68+cg*4;
                r[0]=f.x+acc[j][0]; r[1]=f.y+acc[j][1]; r[2]=f.z+acc[j][2]; r[3]=f.w+acc[j][3];
            }
        }
        __syncthreads();
        for(int idx=t; idx<4096; idx+=256) Ws[idx]=W1v[idx];
        __syncthreads();
        { // MV = (F1i@W1v)*gate -> T slot
            float acc[4][4]; ACC_ZEROF(acc);
            tile_gemm(F0,Ws,64,eg,cg,acc);
#pragma unroll
            for(int j=0;j<4;j++){
                int ln=eg*4+j;
                const float* gg=G+(size_t)ln*68+cg*4;
                float* r=T+(size_t)ln*68+cg*4;
                r[0]=acc[j][0]*gg[0]; r[1]=acc[j][1]*gg[1];
                r[2]=acc[j][2]*gg[2]; r[3]=acc[j][3]*gg[3];
            }
        }
        __syncthreads();
        for(int idx=t; idx<4096; idx+=256) Ws[idx]=W2v[idx];
        __syncthreads();
        { // out1_i = F1i + MV@W2v, interleaved [col][i]
            float acc[4][4]; ACC_ZEROF(acc);
            tile_gemm(T,Ws,64,eg,cg,acc);
#pragma unroll
            for(int j=0;j<4;j++){
                int ln=eg*4+j, n=nb+ln;
                if(n<N){
                    const float* f=F0+(size_t)ln*68+cg*4;
#pragma unroll
                    for(int c=0;c<4;c++)
                        out[(size_t)n*256+64+(cg*4+c)*3+i]=f[c]+acc[j][c];
                }
            }
        }
    }
}

extern "C" void kernel_launch(void* const* d_in, const int* in_sizes, int n_in,
                              void* d_out, int out_size){
    const float* pos   =(const float*)d_in[0];
    const float* embW  =(const float*)d_in[1];
    const float* expw  =(const float*)d_in[2];
    const float* W1    =(const float*)d_in[3];
    const float* b1    =(const float*)d_in[4];
    const float* W2    =(const float*)d_in[5];
    const float* b2    =(const float*)d_in[6];
    const float* Wdeg  =(const float*)d_in[7];
    const float* bdeg  =(const float*)d_in[8];
    const float* Wattn =(const float*)d_in[9];
    const float* battn =(const float*)d_in[10];
    const float* P0    =(const float*)d_in[11];
    const float* P1    =(const float*)d_in[12];
    const float* ad    =(const float*)d_in[13];
    const float* P0o   =(const float*)d_in[14];
    const float* P1o   =(const float*)d_in[15];
    const float* W1s   =(const float*)d_in[16];
    const float* b1s   =(const float*)d_in[17];
    const float* W1v   =(const float*)d_in[18];
    const float* W2s   =(const float*)d_in[19];
    const float* b2s   =(const float*)d_in[20];
    const float* W2v   =(const float*)d_in[21];
    const int*   atom  =(const int*)d_in[22];
    const int*   esrc  =(const int*)d_in[23];
    const int*   edst  =(const int*)d_in[24];
    float* out=(float*)d_out;
    const int N=in_sizes[0]/3;
    const int E=in_sizes[23];

    static int attr_done=0;
    if(!attr_done){
        cudaFuncSetAttribute(k_edge,     cudaFuncAttributeMaxDynamicSharedMemorySize, 51200);
        cudaFuncSetAttribute(k_node_deg, cudaFuncAttributeMaxDynamicSharedMemorySize, 50176);
        cudaFuncSetAttribute(k_out,      cudaFuncAttributeMaxDynamicSharedMemorySize, 88064);
        attr_done=1;
    }

    k_zero<<<512,256>>>(N);
    k_prep<<<8,256>>>(Wdeg,bdeg,expw,P0,P1);
    k_edge<<<(E+63)/64,256,51200>>>(pos,esrc,edst,W1,b1,W2,b2,Wattn,battn,E);
    k_node_deg<<<(N+63)/64,256,50176>>>(embW,atom,N);
    k_msg<<<(E+7)/8,256>>>(esrc,edst,ad,E);
    k_out<<<(N+63)/64,256,88064>>>(P0o,P1o,W1s,b1s,W1v,W2s,b2s,W2v,out,N);
}

// round 13
// speedup vs baseline: 2.9253x; 2.3072x over previous
#include <cuda_runtime.h>
#include <cstdint>
#include <cstddef>

#define NCAP 50048
#define ECAP 800256
#define TBINS 8192
#define TSCALE (8191.0f/5.0f)

static __device__ float g_Y1   [(size_t)ECAP*4];
static __device__ float g_hmidT [(size_t)TBINS*64];
static __device__ float g_wattnT[(size_t)TBINS*320];
static __device__ float g_Hsum [(size_t)NCAP*64];
static __device__ float g_G    [(size_t)NCAP*192];
static __device__ float g_Ysum [(size_t)NCAP*3];
static __device__ float g_deg  [NCAP];
static __device__ float g_f0a  [(size_t)NCAP*64];
static __device__ float g_f1a  [(size_t)NCAP*192];
static __device__ float g_z    [NCAP*8];
static __device__ float g_agg0 [(size_t)NCAP*64];
static __device__ float g_agg1 [(size_t)NCAP*192];
static __device__ float g_M0[4096], g_M1[4096], g_bv0[64], g_bv1[64];

#define RBF_START 0.006737946999085467f
#define RBF_STEP  ((1.0f - RBF_START) / 49.0f)
#define RBF_BETA  (1.0f/((0.04f*(1.0f-RBF_START))*(0.04f*(1.0f-RBF_START))))
#define INV_DEG   0.25f
#define INV_SQRT3 0.5773502691896258f
#define INV_SQRT2 0.7071067811865476f
#define PI_OVER_CUT 0.6283185307179586f

__device__ __forceinline__ float siluf(float x){ return x/(1.f+__expf(-x)); }
__device__ __forceinline__ float sigmf(float x){ return 1.f/(1.f+__expf(-x)); }
__device__ __forceinline__ void red4(float* p, float4 v){
    asm volatile("red.global.add.v4.f32 [%0], {%1,%2,%3,%4};"
                 ::"l"(p),"f"(v.x),"f"(v.y),"f"(v.z),"f"(v.w):"memory");
}

// scalar 4x4 tile GEMM: A rows stride 68, Ws row-major [k][64]
__device__ __forceinline__ void tile_gemm(const float* __restrict__ As,
                                          const float* __restrict__ Ws,
                                          int KK, int eg, int cg, float acc[4][4]){
    for(int k=0;k<KK;k+=4){
        float4 av[4];
#pragma unroll
        for(int j=0;j<4;j++) av[j]=*(const float4*)(As+(size_t)(eg*4+j)*68+k);
        float4 wv[4];
#pragma unroll
        for(int kk=0;kk<4;kk++) wv[kk]=*(const float4*)(Ws+(size_t)(k+kk)*64+cg*4);
#pragma unroll
        for(int j=0;j<4;j++){
            acc[j][0]+=av[j].x*wv[0].x+av[j].y*wv[1].x+av[j].z*wv[2].x+av[j].w*wv[3].x;
            acc[j][1]+=av[j].x*wv[0].y+av[j].y*wv[1].y+av[j].z*wv[2].y+av[j].w*wv[3].y;
            acc[j][2]+=av[j].x*wv[0].z+av[j].y*wv[1].z+av[j].z*wv[2].z+av[j].w*wv[3].z;
            acc[j][3]+=av[j].x*wv[0].w+av[j].y*wv[1].w+av[j].z*wv[2].w+av[j].w*wv[3].w;
        }
    }
}
#define ACC_ZEROF(acc) {_Pragma("unroll") for(int j=0;j<4;j++){_Pragma("unroll") for(int c=0;c<4;c++) acc[j][c]=0.f;}}

__global__ void k_zero(int N){
    size_t i=(size_t)blockIdx.x*blockDim.x+threadIdx.x, st=(size_t)gridDim.x*blockDim.x;
    for(size_t j=i;j<(size_t)N*64;j+=st){ g_Hsum[j]=0.f; g_agg0[j]=0.f; }
    for(size_t j=i;j<(size_t)N*192;j+=st){ g_G[j]=0.f; g_agg1[j]=0.f; }
    for(size_t j=i;j<(size_t)N*8;j+=st) g_z[j]=0.f;
    for(size_t j=i;j<(size_t)N*3;j+=st) g_Ysum[j]=0.f;
    for(size_t j=i;j<(size_t)N;j+=st) g_deg[j]=0.f;
}

__global__ void k_prep(const float* __restrict__ Wdeg, const float* __restrict__ bdeg,
                       const float* __restrict__ ew,
                       const float* __restrict__ P0, const float* __restrict__ P1){
    for(int idx=blockIdx.x*256+threadIdx.x; idx<8320; idx+=8*256){
        if(idx<4096){ int h=idx>>6,d=idx&63; float s=0.f;
            for(int c=0;c<64;c++) s+=Wdeg[h*128+c]*ew[c]*P0[c*64+d];
            g_M0[idx]=s;
        }else if(idx<8192){ int i2=idx-4096,h=i2>>6,d=i2&63; float s=0.f;
            for(int c=0;c<64;c++) s+=Wdeg[h*128+64+c]*ew[c]*P1[c*64+d];
            g_M1[i2]=s;
        }else if(idx<8256){ int d=idx-8192; float s=0.f;
            for(int c=0;c<64;c++) s+=bdeg[c]*ew[c]*P0[c*64+d];
            g_bv0[d]=s;
        }else{ int d=idx-8256; float s=0.f;
            for(int c=0;c<64;c++) s+=bdeg[64+c]*ew[c]*P1[c*64+d];
            g_bv1[d]=s;
        }
    }
}

// K_TABLE: build hmid/wattn tables over dist bins. 64 bins/block, 128 blocks.
// dyn smem: A(64*68)+B(64*68)+Ws(4096) = 51200 B
__global__ __launch_bounds__(256) void k_table(
    const float* __restrict__ W1, const float* __restrict__ b1,
    const float* __restrict__ W2, const float* __restrict__ b2,
    const float* __restrict__ Wattn, const float* __restrict__ battn){
    extern __shared__ float dyn[];
    float* A=dyn; float* B=dyn+64*68; float* Ws=dyn+2*64*68;
    __shared__ float sCut[64], sExp[64];
    const int t=threadIdx.x, bBase=blockIdx.x*64, cg=t&15, eg=t>>4;

    if(t<64){
        float dist=(float)(bBase+t)*(5.0f/8191.0f);
        sCut[t]=(dist<5.0f)?0.5f*(__cosf(dist*PI_OVER_CUT)+1.0f):0.0f;
        sExp[t]=__expf(-dist);
    }
    __syncthreads();
    for(int idx=t; idx<64*52; idx+=256){
        int e=idx/52, k=idx-e*52; float v=0.f;
        if(k<50){ float tt=sExp[e]-(RBF_START+(float)k*RBF_STEP); v=sCut[e]*__expf(-RBF_BETA*tt*tt); }
        A[e*68+k]=v;
    }
    for(int idx=t; idx<52*64; idx+=256){ int r=idx>>6; Ws[idx]=(r<50)?W1[idx]:0.f; }
    __syncthreads();
    { // GEMM1 -> B
        float acc[4][4]; ACC_ZEROF(acc);
        tile_gemm(A,Ws,52,eg,cg,acc);
        float4 bb=*(const float4*)(b1+cg*4);
#pragma unroll
        for(int j=0;j<4;j++){
            float* r=B+(size_t)(eg*4+j)*68+cg*4;
            r[0]=siluf(acc[j][0]+bb.x); r[1]=siluf(acc[j][1]+bb.y);
            r[2]=siluf(acc[j][2]+bb.z); r[3]=siluf(acc[j][3]+bb.w);
        }
    }
    __syncthreads();
    for(int idx=t; idx<4096; idx+=256) Ws[idx]=W2[idx];
    __syncthreads();
    { // GEMM2 -> A (hmid) + store table
        float acc[4][4]; ACC_ZEROF(acc);
        tile_gemm(B,Ws,64,eg,cg,acc);
        float4 bb=*(const float4*)(b2+cg*4);
#pragma unroll
        for(int j=0;j<4;j++){
            float4 h;
            h.x=siluf(acc[j][0]+bb.x); h.y=siluf(acc[j][1]+bb.y);
            h.z=siluf(acc[j][2]+bb.z); h.w=siluf(acc[j][3]+bb.w);
            *(float4*)(A+(size_t)(eg*4+j)*68+cg*4)=h;
            *(float4*)&g_hmidT[(size_t)(bBase+eg*4+j)*64+cg*4]=h;
        }
    }
    for(int p=0;p<5;p++){
        __syncthreads();
        for(int idx=t; idx<4096; idx+=256){
            int r=idx>>6, c=idx&63;
            Ws[idx]=Wattn[(size_t)r*320+p*64+c];
        }
        __syncthreads();
        float acc[4][4]; ACC_ZEROF(acc);
        tile_gemm(A,Ws,64,eg,cg,acc);
        float4 bb=*(const float4*)(battn+p*64+cg*4);
#pragma unroll
        for(int j=0;j<4;j++)
            *(float4*)&g_wattnT[(size_t)(bBase+eg*4+j)*320+p*64+cg*4]=
                make_float4(acc[j][0]+bb.x,acc[j][1]+bb.y,acc[j][2]+bb.z,acc[j][3]+bb.w);
    }
}

// K_GEOM: geometry + hmid table lerp + degree scatter. 64 edges/block.
__global__ __launch_bounds__(256) void k_geom(
    const float* __restrict__ pos, const int* __restrict__ esrc, const int* __restrict__ edst,
    int E){
    __shared__ int sDst[64], sIdx[64];
    __shared__ float sY1[64][4], sFrac[64];
    const int t=threadIdx.x, eBase=blockIdx.x*64;

    if(t<64){
        int ge=eBase+t;
        if(ge<E){
            int s=esrc[ge], d=edst[ge];
            float vx=pos[d*3+0]-pos[s*3+0], vy=pos[d*3+1]-pos[s*3+1], vz=pos[d*3+2]-pos[s*3+2];
            float d2=vx*vx+vy*vy+vz*vz+1e-9f;
            float id=rsqrtf(d2), dist=d2*id;
            float yx=vx*id, yy=vy*id, yz=vz*id;
            sDst[t]=d; sY1[t][0]=yx; sY1[t][1]=yy; sY1[t][2]=yz; sY1[t][3]=0.f;
            float u=fminf(dist*TSCALE, 8191.0f);
            int i0=min((int)u, 8190);
            sIdx[t]=i0; sFrac[t]=u-(float)i0;
            *(float4*)&g_Y1[(size_t)ge*4]=make_float4(yx,yy,yz,dist);
        }else{
            sDst[t]=0; sIdx[t]=0; sFrac[t]=0.f;
            sY1[t][0]=sY1[t][1]=sY1[t][2]=sY1[t][3]=0.f;
        }
    }
    __syncthreads();
    {
        int e=t>>2, q=t&3;
        if(eBase+e<E){
            int d=sDst[e], i0=sIdx[e];
            float f=sFrac[e];
            float yx=sY1[e][0], yy=sY1[e][1], yz=sY1[e][2];
            const float* r0=g_hmidT+(size_t)i0*64;
            const float* r1=r0+64;
#pragma unroll
            for(int m=0;m<4;m++){
                int c=q*16+m*4;
                float4 a=*(const float4*)(r0+c);
                float4 b=*(const float4*)(r1+c);
                float4 h4;
                h4.x=a.x+f*(b.x-a.x); h4.y=a.y+f*(b.y-a.y);
                h4.z=a.z+f*(b.z-a.z); h4.w=a.w+f*(b.w-a.w);
                red4(&g_Hsum[(size_t)d*64+c], h4);
                red4(&g_G[(size_t)d*192+c],     make_float4(h4.x*yx,h4.y*yx,h4.z*yx,h4.w*yx));
                red4(&g_G[(size_t)d*192+64+c],  make_float4(h4.x*yy,h4.y*yy,h4.z*yy,h4.w*yy));
                red4(&g_G[(size_t)d*192+128+c], make_float4(h4.x*yz,h4.y*yz,h4.z*yz,h4.w*yz));
            }
        }
        if(t<64 && eBase+t<E){
            int d=sDst[t];
            atomicAdd(&g_deg[d],1.0f);
            atomicAdd(&g_Ysum[(size_t)d*3+0],sY1[t][0]);
            atomicAdd(&g_Ysum[(size_t)d*3+1],sY1[t][1]);
            atomicAdd(&g_Ysum[(size_t)d*3+2],sY1[t][2]);
        }
    }
}

// K2: batched 64 nodes/block. dyn smem: A(4352)+M0(4096)+M1(4096)=50176B
__global__ __launch_bounds__(256) void k_node_deg(
    const float* __restrict__ embW, const int* __restrict__ atom, int N){
    extern __shared__ float dyn[];
    float* A=dyn; float* M0s=dyn+4352; float* M1s=dyn+8448;
    __shared__ float sbv0[64], sbv1[64], sDeg[64], sYs[3][64];
    __shared__ int sAtom[64];
    const int t=threadIdx.x, nb=blockIdx.x*64, cg=t&15, eg=t>>4;
    for(int idx=t; idx<4096; idx+=256){ M0s[idx]=g_M0[idx]; M1s[idx]=g_M1[idx]; }
    if(t<64){
        sbv0[t]=g_bv0[t]; sbv1[t]=g_bv1[t];
        int n=nb+t; bool v=n<N;
        sDeg[t]=v?g_deg[n]:0.f;
        sYs[0][t]=v?g_Ysum[(size_t)n*3+0]:0.f;
        sYs[1][t]=v?g_Ysum[(size_t)n*3+1]:0.f;
        sYs[2][t]=v?g_Ysum[(size_t)n*3+2]:0.f;
        sAtom[t]=v?atom[n]:0;
    }
    for(int idx=t; idx<4096; idx+=256){
        int n=idx>>6, k=idx&63;
        A[n*68+k]=(nb+n<N)?g_Hsum[(size_t)(nb+n)*64+k]:0.f;
    }
    __syncthreads();
    {
        float acc[4][4]; ACC_ZEROF(acc);
        tile_gemm(A,M0s,64,eg,cg,acc);
#pragma unroll
        for(int j=0;j<4;j++){
            int ln=eg*4+j, n=nb+ln;
            if(n<N){
                float dg=sDeg[ln];
                float4 ev=*(const float4*)(embW+(size_t)sAtom[ln]*64+cg*4);
                float4 o;
                o.x=ev.x+INV_DEG*(acc[j][0]+dg*sbv0[cg*4+0]);
                o.y=ev.y+INV_DEG*(acc[j][1]+dg*sbv0[cg*4+1]);
                o.z=ev.z+INV_DEG*(acc[j][2]+dg*sbv0[cg*4+2]);
                o.w=ev.w+INV_DEG*(acc[j][3]+dg*sbv0[cg*4+3]);
                *(float4*)&g_f0a[(size_t)n*64+cg*4]=o;
            }
        }
    }
    for(int i=0;i<3;i++){
        __syncthreads();
        for(int idx=t; idx<4096; idx+=256){
            int n=idx>>6, k=idx&63;
            A[n*68+k]=(nb+n<N)?g_G[(size_t)(nb+n)*192+i*64+k]:0.f;
        }
        __syncthreads();
        float acc[4][4]; ACC_ZEROF(acc);
        tile_gemm(A,M1s,64,eg,cg,acc);
#pragma unroll
        for(int j=0;j<4;j++){
            int ln=eg*4+j, n=nb+ln;
            if(n<N){
                float ys=sYs[i][ln];
                float4 o;
                o.x=INV_DEG*(acc[j][0]+ys*sbv1[cg*4+0]);
                o.y=INV_DEG*(acc[j][1]+ys*sbv1[cg*4+1]);
                o.z=INV_DEG*(acc[j][2]+ys*sbv1[cg*4+2]);
                o.w=INV_DEG*(acc[j][3]+ys*sbv1[cg*4+3]);
                *(float4*)&g_f1a[(size_t)n*192+i*64+cg*4]=o;
            }
        }
    }
}

// K3: warp-per-edge messages + exp + direct weighted scatter; wattn from table lerp
__global__ __launch_bounds__(256) void k_msg(
    const int* __restrict__ esrc, const int* __restrict__ edst,
    const float* __restrict__ ad, int E){
    __shared__ float sMsg[8][256];
    const int w=threadIdx.x>>5, lane=threadIdx.x&31;
    const int e=blockIdx.x*8+w;
    if(e>=E) return;
    const int src=esrc[e], dst=edst[e];
    float4 y4=*(const float4*)&g_Y1[(size_t)e*4];
    const float yx=y4.x, yy=y4.y, yz=y4.z, dist=y4.w;
    float u=fminf(dist*TSCALE, 8191.0f);
    int i0=min((int)u, 8190);
    float f=u-(float)i0;
    const float* r0=g_wattnT+(size_t)i0*320;
    const float* r1=r0+320;
    const int c0=lane, c1=lane+32;
    float s0a=g_f0a[(size_t)src*64+c0], s0b=g_f0a[(size_t)src*64+c1];
    float s1a0=g_f1a[(size_t)src*192+c0],     s1b0=g_f1a[(size_t)src*192+c1];
    float s1a1=g_f1a[(size_t)src*192+64+c0],  s1b1=g_f1a[(size_t)src*192+64+c1];
    float s1a2=g_f1a[(size_t)src*192+128+c0], s1b2=g_f1a[(size_t)src*192+128+c1];
    float w0a=r0[c0]+f*(r1[c0]-r0[c0]),         w0b=r0[c1]+f*(r1[c1]-r0[c1]);
    float w1a=r0[64+c0]+f*(r1[64+c0]-r0[64+c0]), w1b=r0[64+c1]+f*(r1[64+c1]-r0[64+c1]);
    float w2a=r0[128+c0]+f*(r1[128+c0]-r0[128+c0]), w2b=r0[128+c1]+f*(r1[128+c1]-r0[128+c1]);
    float w3a=r0[192+c0]+f*(r1[192+c0]-r0[192+c0]), w3b=r0[192+c1]+f*(r1[192+c1]-r0[192+c1]);
    float w4a=r0[256+c0]+f*(r1[256+c0]-r0[256+c0]), w4b=r0[256+c1]+f*(r1[256+c1]-r0[256+c1]);
    float d1a=s1a0*yx+s1a1*yy+s1a2*yz;
    float d1b=s1b0*yx+s1b1*yy+s1b2*yz;
    float m0a=w0a*s0a+w3a*d1a*INV_SQRT3;
    float m0b=w0b*s0b+w3b*d1b*INV_SQRT3;
    float cxa=s1a1*yz-s1a2*yy, cya=s1a2*yx-s1a0*yz, cza=s1a0*yy-s1a1*yx;
    float cxb=s1b1*yz-s1b2*yy, cyb=s1b2*yx-s1b0*yz, czb=s1b0*yy-s1b1*yx;
    float m1a0=w1a*s0a*yx+w2a*s1a0+w4a*cxa*INV_SQRT2;
    float m1a1=w1a*s0a*yy+w2a*s1a1+w4a*cya*INV_SQRT2;
    float m1a2=w1a*s0a*yz+w2a*s1a2+w4a*cza*INV_SQRT2;
    float m1b0=w1b*s0b*yx+w2b*s1b0+w4b*cxb*INV_SQRT2;
    float m1b1=w1b*s0b*yy+w2b*s1b1+w4b*cyb*INV_SQRT2;
    float m1b2=w1b*s0b*yz+w2b*s1b2+w4b*czb*INV_SQRT2;
    float slra=0.2f*m0a+0.8f*m0a*sigmf(m0a);
    float slrb=0.2f*m0b+0.8f*m0b*sigmf(m0b);
    float p0=slra*__ldg(&ad[c0]);
    float p1=slrb*__ldg(&ad[c1]);
#pragma unroll
    for(int off=1;off<8;off<<=1){
        p0+=__shfl_xor_sync(0xffffffffu,p0,off);
        p1+=__shfl_xor_sync(0xffffffffu,p1,off);
    }
    float ea0=__expf(p0), ea1=__expf(p1);
    if((lane&7)==0){
        atomicAdd(&g_z[dst*8+(lane>>3)],  ea0);
        atomicAdd(&g_z[dst*8+4+(lane>>3)],ea1);
    }
    float* myMsg=sMsg[w];
    myMsg[lane]     =ea0*m0a;  myMsg[lane+32]    =ea1*m0b;
    myMsg[64+lane]  =ea0*m1a0; myMsg[64+lane+32] =ea1*m1b0;
    myMsg[128+lane] =ea0*m1a1; myMsg[128+lane+32]=ea1*m1b1;
    myMsg[192+lane] =ea0*m1a2; myMsg[192+lane+32]=ea1*m1b2;
    __syncwarp();
#pragma unroll
    for(int rq=0;rq<2;rq++){
        int q=lane+rq*32;
        float* dp;
        if(q<16) dp=g_agg0+(size_t)dst*64+q*4;
        else{ int rr=q-16, i=rr>>4, cq=rr&15; dp=g_agg1+(size_t)dst*192+i*64+cq*4; }
        red4(dp, *(const float4*)(myMsg+q*4));
    }
}

// K6: batched 64 nodes/block, tile GEMMs. dyn smem 88064 B
__global__ __launch_bounds__(256) void k_out(
    const float* __restrict__ P0o, const float* __restrict__ P1o,
    const float* __restrict__ W1s, const float* __restrict__ b1s,
    const float* __restrict__ W1v, const float* __restrict__ W2s,
    const float* __restrict__ b2s, const float* __restrict__ W2v,
    float* __restrict__ out, int N){
    extern __shared__ float dyn[];
    float* A=dyn; float* F0=dyn+4352; float* T=dyn+8704; float* G=dyn+13056;
    float* Ws=dyn+17408; float* IZ=dyn+21504;
    const int t=threadIdx.x, nb=blockIdx.x*64, cg=t&15, eg=t>>4;

    for(int idx=t; idx<512; idx+=256){
        int n=idx>>3, h=idx&7;
        float z=(nb+n<N)?g_z[(nb+n)*8+h]:0.f;
        IZ[idx]=(z>0.f)?1.f/z:0.f;
    }
    for(int idx=t; idx<4096; idx+=256) Ws[idx]=P0o[idx];
    __syncthreads();
    for(int idx=t; idx<4096; idx+=256){
        int n=idx>>6, c=idx&63;
        A[n*68+c]=(nb+n<N)?g_agg0[(size_t)(nb+n)*64+c]*IZ[n*8+(c>>3)]:0.f;
    }
    __syncthreads();
    {
        float acc[4][4]; ACC_ZEROF(acc);
        tile_gemm(A,Ws,64,eg,cg,acc);
#pragma unroll
        for(int j=0;j<4;j++){
            int ln=eg*4+j, n=nb+ln;
            float4 fv=(n<N)?*(const float4*)&g_f0a[(size_t)n*64+cg*4]:make_float4(0,0,0,0);
            float* r=F0+(size_t)ln*68+cg*4;
            r[0]=fv.x+acc[j][0]; r[1]=fv.y+acc[j][1]; r[2]=fv.z+acc[j][2]; r[3]=fv.w+acc[j][3];
        }
    }
    __syncthreads();
    for(int idx=t; idx<4096; idx+=256) Ws[idx]=W1s[(size_t)(idx>>6)*128+(idx&63)];
    __syncthreads();
    {
        float acc[4][4]; ACC_ZEROF(acc);
        tile_gemm(F0,Ws,64,eg,cg,acc);
        float4 bb=*(const float4*)&b1s[cg*4];
#pragma unroll
        for(int j=0;j<4;j++){
            float* r=T+(size_t)(eg*4+j)*68+cg*4;
            r[0]=siluf(acc[j][0]+bb.x); r[1]=siluf(acc[j][1]+bb.y);
            r[2]=siluf(acc[j][2]+bb.z); r[3]=siluf(acc[j][3]+bb.w);
        }
    }
    __syncthreads();
    for(int idx=t; idx<4096; idx+=256) Ws[idx]=W1s[(size_t)(idx>>6)*128+64+(idx&63)];
    __syncthreads();
    {
        float acc[4][4]; ACC_ZEROF(acc);
        tile_gemm(F0,Ws,64,eg,cg,acc);
        float4 bb=*(const float4*)&b1s[64+cg*4];
#pragma unroll
        for(int j=0;j<4;j++){
            float* r=G+(size_t)(eg*4+j)*68+cg*4;
            r[0]=sigmf(acc[j][0]+bb.x); r[1]=sigmf(acc[j][1]+bb.y);
            r[2]=sigmf(acc[j][2]+bb.z); r[3]=sigmf(acc[j][3]+bb.w);
        }
    }
    __syncthreads();
    for(int idx=t; idx<4096; idx+=256) Ws[idx]=W2s[idx];
    __syncthreads();
    {
        float acc[4][4]; ACC_ZEROF(acc);
        tile_gemm(T,Ws,64,eg,cg,acc);
        float4 bb=*(const float4*)&b2s[cg*4];
#pragma unroll
        for(int j=0;j<4;j++){
            int ln=eg*4+j, n=nb+ln;
            if(n<N){
                const float* fv=F0+(size_t)ln*68+cg*4;
                *(float4*)&out[(size_t)n*256+cg*4]=make_float4(
                    fv[0]+acc[j][0]+bb.x, fv[1]+acc[j][1]+bb.y,
                    fv[2]+acc[j][2]+bb.z, fv[3]+acc[j][3]+bb.w);
            }
        }
    }
    for(int i=0;i<3;i++){
        __syncthreads();
        for(int idx=t; idx<4096; idx+=256) Ws[idx]=P1o[idx];
        for(int idx=t; idx<4096; idx+=256){
            int n=idx>>6, c=idx&63;
            A[n*68+c]=(nb+n<N)?g_agg1[(size_t)(nb+n)*192+i*64+c]*IZ[n*8+(c>>3)]:0.f;
        }
        __syncthreads();
        {
            float acc[4][4]; ACC_ZEROF(acc);
            tile_gemm(A,Ws,64,eg,cg,acc);
#pragma unroll
            for(int j=0;j<4;j++){
                int ln=eg*4+j, n=nb+ln;
                float4 fv=(n<N)?*(const float4*)&g_f1a[(size_t)n*192+i*64+cg*4]:make_float4(0,0,0,0);
                float* r=F0+(size_t)ln*68+cg*4;
                r[0]=fv.x+acc[j][0]; r[1]=fv.y+acc[j][1]; r[2]=fv.z+acc[j][2]; r[3]=fv.w+acc[j][3];
            }
        }
        __syncthreads();
        for(int idx=t; idx<4096; idx+=256) Ws[idx]=W1v[idx];
        __syncthreads();
        {
            float acc[4][4]; ACC_ZEROF(acc);
            tile_gemm(F0,Ws,64,eg,cg,acc);
#pragma unroll
            for(int j=0;j<4;j++){
                int ln=eg*4+j;
                const float* gg=G+(size_t)ln*68+cg*4;
                float* r=T+(size_t)ln*68+cg*4;
                r[0]=acc[j][0]*gg[0]; r[1]=acc[j][1]*gg[1];
                r[2]=acc[j][2]*gg[2]; r[3]=acc[j][3]*gg[3];
            }
        }
        __syncthreads();
        for(int idx=t; idx<4096; idx+=256) Ws[idx]=W2v[idx];
        __syncthreads();
        {
            float acc[4][4]; ACC_ZEROF(acc);
            tile_gemm(T,Ws,64,eg,cg,acc);
#pragma unroll
            for(int j=0;j<4;j++){
                int ln=eg*4+j, n=nb+ln;
                if(n<N){
                    const float* fv=F0+(size_t)ln*68+cg*4;
#pragma unroll
                    for(int c=0;c<4;c++)
                        out[(size_t)n*256+64+(cg*4+c)*3+i]=fv[c]+acc[j][c];
                }
            }
        }
    }
}

extern "C" void kernel_launch(void* const* d_in, const int* in_sizes, int n_in,
                              void* d_out, int out_size){
    const float* pos   =(const float*)d_in[0];
    const float* embW  =(const float*)d_in[1];
    const float* expw  =(const float*)d_in[2];
    const float* W1    =(const float*)d_in[3];
    const float* b1    =(const float*)d_in[4];
    const float* W2    =(const float*)d_in[5];
    const float* b2    =(const float*)d_in[6];
    const float* Wdeg  =(const float*)d_in[7];
    const float* bdeg  =(const float*)d_in[8];
    const float* Wattn =(const float*)d_in[9];
    const float* battn =(const float*)d_in[10];
    const float* P0    =(const float*)d_in[11];
    const float* P1    =(const float*)d_in[12];
    const float* ad    =(const float*)d_in[13];
    const float* P0o   =(const float*)d_in[14];
    const float* P1o   =(const float*)d_in[15];
    const float* W1s   =(const float*)d_in[16];
    const float* b1s   =(const float*)d_in[17];
    const float* W1v   =(const float*)d_in[18];
    const float* W2s   =(const float*)d_in[19];
    const float* b2s   =(const float*)d_in[20];
    const float* W2v   =(const float*)d_in[21];
    const int*   atom  =(const int*)d_in[22];
    const int*   esrc  =(const int*)d_in[23];
    const int*   edst  =(const int*)d_in[24];
    float* out=(float*)d_out;
    const int N=in_sizes[0]/3;
    const int E=in_sizes[23];

    static int attr_done=0;
    if(!attr_done){
        cudaFuncSetAttribute(k_table,    cudaFuncAttributeMaxDynamicSharedMemorySize, 51200);
        cudaFuncSetAttribute(k_node_deg, cudaFuncAttributeMaxDynamicSharedMemorySize, 50176);
        cudaFuncSetAttribute(k_out,      cudaFuncAttributeMaxDynamicSharedMemorySize, 88064);
        attr_done=1;
    }

    k_zero<<<512,256>>>(N);
    k_prep<<<8,256>>>(Wdeg,bdeg,expw,P0,P1);
    k_table<<<TBINS/64,256,51200>>>(W1,b1,W2,b2,Wattn,battn);
    k_geom<<<(E+63)/64,256>>>(pos,esrc,edst,E);
    k_node_deg<<<(N+63)/64,256,50176>>>(embW,atom,N);
    k_msg<<<(E+7)/8,256>>>(esrc,edst,ad,E);
    k_out<<<(N+63)/64,256,88064>>>(P0o,P1o,W1s,b1s,W1v,W2s,b2s,W2v,out,N);
}